// round 8
// baseline (speedup 1.0000x reference)
#include <cuda_runtime.h>
#include <cuda_bf16.h>
#include <cstdint>

#define KMIX 10
#define TILE_PIX 256
#define THREADS 256
#define NSTAGES 2

#define STAGE_BYTES (TILE_PIX * (3 * KMIX + 2) * 4)          // 32768
#define OFF_PI 0
#define OFF_MU (TILE_PIX * KMIX * 4)
#define OFF_LS (2 * TILE_PIX * KMIX * 4)
#define OFF_U  (3 * TILE_PIX * KMIX * 4)
#define OFF_E  (3 * TILE_PIX * KMIX * 4 + TILE_PIX * 4)
#define OFF_MBAR (NSTAGES * STAGE_BYTES)                     // 65536
#define SMEM_TOTAL (OFF_MBAR + NSTAGES * 8)

extern __shared__ __align__(16) char dynsmem[];

__device__ __forceinline__ uint32_t smem_u32(const void* p) {
    uint64_t t;
    asm("cvta.to.shared.u64 %0, %1;" : "=l"(t) : "l"(p));
    return (uint32_t)t;
}

__device__ __forceinline__ void mbar_wait(uint32_t mbar, uint32_t parity) {
    uint32_t done;
    asm volatile(
        "{\n\t.reg .pred p;\n\t"
        "mbarrier.try_wait.parity.acquire.cta.shared::cta.b64 p, [%1], %2;\n\t"
        "selp.b32 %0, 1, 0, p;\n\t}"
        : "=r"(done) : "r"(mbar), "r"(parity) : "memory");
    while (!done) {
        asm volatile(
            "{\n\t.reg .pred p;\n\t"
            "mbarrier.try_wait.parity.acquire.cta.shared::cta.b64 p, [%1], %2, 0x989680;\n\t"
            "selp.b32 %0, 1, 0, p;\n\t}"
            : "=r"(done) : "r"(mbar), "r"(parity) : "memory");
    }
}

__device__ __forceinline__ void prefetch_tile(
    uint32_t stage_base, uint32_t mbar, long tile,
    const float* __restrict__ mu, const float* __restrict__ log_std,
    const float* __restrict__ pi_logits, const float* __restrict__ u_cat,
    const float* __restrict__ eps)
{
    const uint32_t row_bytes = TILE_PIX * KMIX * 4;
    const uint32_t vec_bytes = TILE_PIX * 4;
    const uint32_t total_tx  = 3 * row_bytes + 2 * vec_bytes;

    asm volatile("mbarrier.arrive.expect_tx.shared.b64 _, [%0], %1;"
                 :: "r"(mbar), "r"(total_tx) : "memory");

    long base = tile * TILE_PIX;
#define BULK_CP(off, src, nbytes)                                               \
    asm volatile("cp.async.bulk.shared::cta.global.mbarrier::complete_tx::bytes " \
                 "[%0], [%1], %2, [%3];"                                        \
                 :: "r"(stage_base + (off)), "l"(src), "r"(nbytes), "r"(mbar) : "memory")

    BULK_CP(OFF_PI, pi_logits + base * KMIX, row_bytes);
    BULK_CP(OFF_MU, mu        + base * KMIX, row_bytes);
    BULK_CP(OFF_LS, log_std   + base * KMIX, row_bytes);
    BULK_CP(OFF_U,  u_cat     + base,        vec_bytes);
    BULK_CP(OFF_E,  eps       + base,        vec_bytes);
#undef BULK_CP
}

__global__ void __launch_bounds__(THREADS) melnet_gmm_pipe_kernel(
    const float* __restrict__ mu,
    const float* __restrict__ log_std,
    const float* __restrict__ pi_logits,
    const float* __restrict__ u_cat,
    const float* __restrict__ eps,
    float* __restrict__ out,
    int ntiles)
{
    const int tid = threadIdx.x;
    const uint32_t smem_base = smem_u32(dynsmem);
    const uint32_t mbar0 = smem_base + OFF_MBAR;

    if (tid == 0) {
        asm volatile("mbarrier.init.shared.b64 [%0], 1;" :: "r"(mbar0)     : "memory");
        asm volatile("mbarrier.init.shared.b64 [%0], 1;" :: "r"(mbar0 + 8) : "memory");
        asm volatile("fence.proxy.async.shared::cta;" ::: "memory");
    }
    __syncthreads();

    long t0 = blockIdx.x;
    if (t0 >= ntiles) return;
    const long stride = gridDim.x;

    // prologue: prefetch first tile into stage 0
    if (tid == 0)
        prefetch_tile(smem_base + 0 * STAGE_BYTES, mbar0, t0,
                      mu, log_std, pi_logits, u_cat, eps);

    uint32_t phase[NSTAGES] = {0, 0};
    int it = 0;
    for (long t = t0; t < ntiles; t += stride, it++) {
        const int s = it & 1;
        const uint32_t stage_base = smem_base + s * STAGE_BYTES;
        const uint32_t mbar_s = mbar0 + s * 8;

        // prefetch next tile into the other stage (freed by prev iter's syncthreads)
        long tnext = t + stride;
        if (tid == 0 && tnext < ntiles)
            prefetch_tile(smem_base + (s ^ 1) * STAGE_BYTES, mbar0 + (s ^ 1) * 8,
                          tnext, mu, log_std, pi_logits, u_cat, eps);

        mbar_wait(mbar_s, phase[s]);
        phase[s] ^= 1;

        // ---- compute pixel `tid` of this tile, entirely from smem ----
        const float* s_pi = (const float*)(dynsmem + s * STAGE_BYTES + OFF_PI);
        const float* s_mu = (const float*)(dynsmem + s * STAGE_BYTES + OFF_MU);
        const float* s_ls = (const float*)(dynsmem + s * STAGE_BYTES + OFF_LS);
        const float* s_u  = (const float*)(dynsmem + s * STAGE_BYTES + OFF_U);
        const float* s_e  = (const float*)(dynsmem + s * STAGE_BYTES + OFF_E);

        const float2* sp = reinterpret_cast<const float2*>(s_pi) + tid * 5;
        float2 q0 = sp[0], q1 = sp[1], q2 = sp[2], q3 = sp[3], q4 = sp[4];
        float u = s_u[tid];

        float l[KMIX] = { q0.x, q0.y, q1.x, q1.y, q2.x,
                          q2.y, q3.x, q3.y, q4.x, q4.y };

        // softmax + inverse-CDF pick, arithmetic byte-identical to reference
        float m = l[0];
#pragma unroll
        for (int j = 1; j < KMIX; j++) m = fmaxf(m, l[j]);

        float e[KMIX];
        float S = 0.0f;
#pragma unroll
        for (int j = 0; j < KMIX; j++) {
            e[j] = expf(__fadd_rn(l[j], -m));
            S = __fadd_rn(S, e[j]);
        }

        float cdf = 0.0f;
        int k = 0;
#pragma unroll
        for (int j = 0; j < KMIX; j++) {
            float pj = __fdiv_rn(e[j], S);   // exact IEEE division, matching reference
            cdf = __fadd_rn(cdf, pj);
            k += (cdf < u) ? 1 : 0;
        }
        if (k > KMIX - 1) k = KMIX - 1;

        float mu_k = s_mu[tid * KMIX + k];   // bit-identical to a global gather
        float ls_k = s_ls[tid * KMIX + k];
        float ep   = s_e[tid];

        out[t * TILE_PIX + tid] = __fadd_rn(mu_k, __fmul_rn(expf(ls_k), ep));

        __syncthreads();   // buffer s must be fully consumed before its refill
    }
}

extern "C" void kernel_launch(void* const* d_in, const int* in_sizes, int n_in,
                              void* d_out, int out_size)
{
    // metadata order: mu, log_std, pi_logits, u_cat, eps
    const float* mu        = (const float*)d_in[0];
    const float* log_std   = (const float*)d_in[1];
    const float* pi_logits = (const float*)d_in[2];
    const float* u_cat     = (const float*)d_in[3];
    const float* eps       = (const float*)d_in[4];
    float* out = (float*)d_out;

    int n = in_sizes[3];                 // 4,194,304 — divisible by TILE_PIX
    int ntiles = n / TILE_PIX;           // 16384

    static bool attr_set = false;
    if (!attr_set) {
        cudaFuncSetAttribute(melnet_gmm_pipe_kernel,
                             cudaFuncAttributeMaxDynamicSharedMemorySize,
                             SMEM_TOTAL);
        attr_set = true;
    }

    int grid = 152 * 3;                  // persistent: 3 CTAs/SM on 152 SMs
    if (grid > ntiles) grid = ntiles;

    melnet_gmm_pipe_kernel<<<grid, THREADS, SMEM_TOTAL>>>(
        mu, log_std, pi_logits, u_cat, eps, out, ntiles);
}

// round 9
// speedup vs baseline: 1.0712x; 1.0712x over previous
#include <cuda_runtime.h>
#include <cuda_bf16.h>
#include <cstdint>

#define KMIX 10
#define TILE_PIX 128          // pixels per CTA
#define THREADS 128

// static smem tile: pi/mu/ls 5120 B each, u/eps 512 B each, + mbarrier
__global__ void __launch_bounds__(THREADS) melnet_gmm_bulk128_kernel(
    const float* __restrict__ mu,
    const float* __restrict__ log_std,
    const float* __restrict__ pi_logits,
    const float* __restrict__ u_cat,
    const float* __restrict__ eps,
    float* __restrict__ out,
    int n)
{
    __shared__ __align__(16) float s_pi[TILE_PIX * KMIX];
    __shared__ __align__(16) float s_mu[TILE_PIX * KMIX];
    __shared__ __align__(16) float s_ls[TILE_PIX * KMIX];
    __shared__ __align__(16) float s_u [TILE_PIX];
    __shared__ __align__(16) float s_e [TILE_PIX];
    __shared__ __align__(8)  unsigned long long s_mbar;

    const int tid  = threadIdx.x;
    const long base = (long)blockIdx.x * TILE_PIX;

    uint32_t mbar;
    {
        uint64_t tmp;
        asm("cvta.to.shared.u64 %0, %1;" : "=l"(tmp) : "l"((void*)&s_mbar));
        mbar = (uint32_t)tmp;
    }

    // tid0: init -> fence -> issue immediately (self-ordered); others sync then wait
    if (tid == 0) {
        asm volatile("mbarrier.init.shared.b64 [%0], 1;" :: "r"(mbar) : "memory");
        asm volatile("fence.proxy.async.shared::cta;" ::: "memory");

        const uint32_t row_bytes = TILE_PIX * KMIX * 4;   // 5120
        const uint32_t vec_bytes = TILE_PIX * 4;          // 512
        const uint32_t total_tx  = 3 * row_bytes + 2 * vec_bytes;
        asm volatile("mbarrier.arrive.expect_tx.shared.b64 _, [%0], %1;"
                     :: "r"(mbar), "r"(total_tx) : "memory");

        uint32_t d_pi, d_mu, d_ls, d_u, d_e;
        { uint64_t t; asm("cvta.to.shared.u64 %0, %1;" : "=l"(t) : "l"((void*)s_pi)); d_pi = (uint32_t)t; }
        { uint64_t t; asm("cvta.to.shared.u64 %0, %1;" : "=l"(t) : "l"((void*)s_mu)); d_mu = (uint32_t)t; }
        { uint64_t t; asm("cvta.to.shared.u64 %0, %1;" : "=l"(t) : "l"((void*)s_ls)); d_ls = (uint32_t)t; }
        { uint64_t t; asm("cvta.to.shared.u64 %0, %1;" : "=l"(t) : "l"((void*)s_u )); d_u  = (uint32_t)t; }
        { uint64_t t; asm("cvta.to.shared.u64 %0, %1;" : "=l"(t) : "l"((void*)s_e )); d_e  = (uint32_t)t; }

#define BULK_CP(dst, src, nbytes)                                               \
        asm volatile("cp.async.bulk.shared::cta.global.mbarrier::complete_tx::bytes " \
                     "[%0], [%1], %2, [%3];"                                    \
                     :: "r"(dst), "l"(src), "r"(nbytes), "r"(mbar) : "memory")

        BULK_CP(d_pi, pi_logits + base * KMIX, row_bytes);
        BULK_CP(d_mu, mu        + base * KMIX, row_bytes);
        BULK_CP(d_ls, log_std   + base * KMIX, row_bytes);
        BULK_CP(d_u,  u_cat     + base,        vec_bytes);
        BULK_CP(d_e,  eps       + base,        vec_bytes);
#undef BULK_CP
    }
    __syncthreads();   // init (and issue) visible to all before waiting

    // wait for the tile (acquire ordering for subsequent LDS)
    {
        uint32_t done;
        asm volatile(
            "{\n\t.reg .pred p;\n\t"
            "mbarrier.try_wait.parity.acquire.cta.shared::cta.b64 p, [%1], 0;\n\t"
            "selp.b32 %0, 1, 0, p;\n\t}"
            : "=r"(done) : "r"(mbar) : "memory");
        while (!done) {
            asm volatile(
                "{\n\t.reg .pred p;\n\t"
                "mbarrier.try_wait.parity.acquire.cta.shared::cta.b64 p, [%1], 0, 0x989680;\n\t"
                "selp.b32 %0, 1, 0, p;\n\t}"
                : "=r"(done) : "r"(mbar) : "memory");
        }
    }

    // ---- compute pixel `tid` entirely from smem ----
    const float2* sp = reinterpret_cast<const float2*>(s_pi) + tid * 5;
    float2 q0 = sp[0], q1 = sp[1], q2 = sp[2], q3 = sp[3], q4 = sp[4];
    float u = s_u[tid];

    float l[KMIX] = { q0.x, q0.y, q1.x, q1.y, q2.x,
                      q2.y, q3.x, q3.y, q4.x, q4.y };

    // softmax + inverse-CDF pick, arithmetic byte-identical to the reference
    float m = l[0];
#pragma unroll
    for (int j = 1; j < KMIX; j++) m = fmaxf(m, l[j]);

    float e[KMIX];
    float S = 0.0f;
#pragma unroll
    for (int j = 0; j < KMIX; j++) {
        e[j] = expf(__fadd_rn(l[j], -m));
        S = __fadd_rn(S, e[j]);
    }

    float cdf = 0.0f;
    int k = 0;
#pragma unroll
    for (int j = 0; j < KMIX; j++) {
        float pj = __fdiv_rn(e[j], S);     // exact IEEE division, matching reference
        cdf = __fadd_rn(cdf, pj);
        k += (cdf < u) ? 1 : 0;
    }
    if (k > KMIX - 1) k = KMIX - 1;

    float mu_k = s_mu[tid * KMIX + k];     // bit-identical to a global gather
    float ls_k = s_ls[tid * KMIX + k];
    float ep   = s_e[tid];

    long p = base + tid;
    if (p < n)
        out[p] = __fadd_rn(mu_k, __fmul_rn(expf(ls_k), ep));
}

extern "C" void kernel_launch(void* const* d_in, const int* in_sizes, int n_in,
                              void* d_out, int out_size)
{
    // metadata order: mu, log_std, pi_logits, u_cat, eps
    const float* mu        = (const float*)d_in[0];
    const float* log_std   = (const float*)d_in[1];
    const float* pi_logits = (const float*)d_in[2];
    const float* u_cat     = (const float*)d_in[3];
    const float* eps       = (const float*)d_in[4];
    float* out = (float*)d_out;

    int n = in_sizes[3];                   // 4,194,304 — divisible by TILE_PIX
    int tiles = (n + TILE_PIX - 1) / TILE_PIX;   // 32768

    melnet_gmm_bulk128_kernel<<<tiles, THREADS>>>(mu, log_std, pi_logits,
                                                  u_cat, eps, out, n);
}

// round 10
// speedup vs baseline: 1.0745x; 1.0031x over previous
#include <cuda_runtime.h>
#include <cuda_bf16.h>
#include <cstdint>

#define KMIX 10
#define TILE_PIX 64           // pixels per CTA
#define THREADS 64

// static smem tile: pi/mu/ls 2560 B each, u/eps 256 B each, + mbarrier
__global__ void __launch_bounds__(THREADS) melnet_gmm_bulk64_kernel(
    const float* __restrict__ mu,
    const float* __restrict__ log_std,
    const float* __restrict__ pi_logits,
    const float* __restrict__ u_cat,
    const float* __restrict__ eps,
    float* __restrict__ out,
    int n)
{
    __shared__ __align__(16) float s_pi[TILE_PIX * KMIX];
    __shared__ __align__(16) float s_mu[TILE_PIX * KMIX];
    __shared__ __align__(16) float s_ls[TILE_PIX * KMIX];
    __shared__ __align__(16) float s_u [TILE_PIX];
    __shared__ __align__(16) float s_e [TILE_PIX];
    __shared__ __align__(8)  unsigned long long s_mbar;

    const int tid  = threadIdx.x;
    const long base = (long)blockIdx.x * TILE_PIX;

    uint32_t mbar;
    {
        uint64_t tmp;
        asm("cvta.to.shared.u64 %0, %1;" : "=l"(tmp) : "l"((void*)&s_mbar));
        mbar = (uint32_t)tmp;
    }

    // tid0: init -> fence -> issue immediately (self-ordered); others sync then wait
    if (tid == 0) {
        asm volatile("mbarrier.init.shared.b64 [%0], 1;" :: "r"(mbar) : "memory");
        asm volatile("fence.proxy.async.shared::cta;" ::: "memory");

        const uint32_t row_bytes = TILE_PIX * KMIX * 4;   // 2560
        const uint32_t vec_bytes = TILE_PIX * 4;          // 256
        const uint32_t total_tx  = 3 * row_bytes + 2 * vec_bytes;
        asm volatile("mbarrier.arrive.expect_tx.shared.b64 _, [%0], %1;"
                     :: "r"(mbar), "r"(total_tx) : "memory");

        uint32_t d_pi, d_mu, d_ls, d_u, d_e;
        { uint64_t t; asm("cvta.to.shared.u64 %0, %1;" : "=l"(t) : "l"((void*)s_pi)); d_pi = (uint32_t)t; }
        { uint64_t t; asm("cvta.to.shared.u64 %0, %1;" : "=l"(t) : "l"((void*)s_mu)); d_mu = (uint32_t)t; }
        { uint64_t t; asm("cvta.to.shared.u64 %0, %1;" : "=l"(t) : "l"((void*)s_ls)); d_ls = (uint32_t)t; }
        { uint64_t t; asm("cvta.to.shared.u64 %0, %1;" : "=l"(t) : "l"((void*)s_u )); d_u  = (uint32_t)t; }
        { uint64_t t; asm("cvta.to.shared.u64 %0, %1;" : "=l"(t) : "l"((void*)s_e )); d_e  = (uint32_t)t; }

#define BULK_CP(dst, src, nbytes)                                               \
        asm volatile("cp.async.bulk.shared::cta.global.mbarrier::complete_tx::bytes " \
                     "[%0], [%1], %2, [%3];"                                    \
                     :: "r"(dst), "l"(src), "r"(nbytes), "r"(mbar) : "memory")

        BULK_CP(d_pi, pi_logits + base * KMIX, row_bytes);
        BULK_CP(d_mu, mu        + base * KMIX, row_bytes);
        BULK_CP(d_ls, log_std   + base * KMIX, row_bytes);
        BULK_CP(d_u,  u_cat     + base,        vec_bytes);
        BULK_CP(d_e,  eps       + base,        vec_bytes);
#undef BULK_CP
    }
    __syncthreads();   // init (and issue) visible to all before waiting

    // wait for the tile (acquire ordering for subsequent LDS)
    {
        uint32_t done;
        asm volatile(
            "{\n\t.reg .pred p;\n\t"
            "mbarrier.try_wait.parity.acquire.cta.shared::cta.b64 p, [%1], 0;\n\t"
            "selp.b32 %0, 1, 0, p;\n\t}"
            : "=r"(done) : "r"(mbar) : "memory");
        while (!done) {
            asm volatile(
                "{\n\t.reg .pred p;\n\t"
                "mbarrier.try_wait.parity.acquire.cta.shared::cta.b64 p, [%1], 0, 0x989680;\n\t"
                "selp.b32 %0, 1, 0, p;\n\t}"
                : "=r"(done) : "r"(mbar) : "memory");
        }
    }

    // ---- compute pixel `tid` entirely from smem ----
    const float2* sp = reinterpret_cast<const float2*>(s_pi) + tid * 5;
    float2 q0 = sp[0], q1 = sp[1], q2 = sp[2], q3 = sp[3], q4 = sp[4];
    float u = s_u[tid];

    float l[KMIX] = { q0.x, q0.y, q1.x, q1.y, q2.x,
                      q2.y, q3.x, q3.y, q4.x, q4.y };

    // softmax + inverse-CDF pick, arithmetic byte-identical to the reference
    float m = l[0];
#pragma unroll
    for (int j = 1; j < KMIX; j++) m = fmaxf(m, l[j]);

    float e[KMIX];
    float S = 0.0f;
#pragma unroll
    for (int j = 0; j < KMIX; j++) {
        e[j] = expf(__fadd_rn(l[j], -m));
        S = __fadd_rn(S, e[j]);
    }

    float cdf = 0.0f;
    int k = 0;
#pragma unroll
    for (int j = 0; j < KMIX; j++) {
        float pj = __fdiv_rn(e[j], S);     // exact IEEE division, matching reference
        cdf = __fadd_rn(cdf, pj);
        k += (cdf < u) ? 1 : 0;
    }
    if (k > KMIX - 1) k = KMIX - 1;

    float mu_k = s_mu[tid * KMIX + k];     // bit-identical to a global gather
    float ls_k = s_ls[tid * KMIX + k];
    float ep   = s_e[tid];

    long p = base + tid;
    if (p < n)
        out[p] = __fadd_rn(mu_k, __fmul_rn(expf(ls_k), ep));
}

extern "C" void kernel_launch(void* const* d_in, const int* in_sizes, int n_in,
                              void* d_out, int out_size)
{
    // metadata order: mu, log_std, pi_logits, u_cat, eps
    const float* mu        = (const float*)d_in[0];
    const float* log_std   = (const float*)d_in[1];
    const float* pi_logits = (const float*)d_in[2];
    const float* u_cat     = (const float*)d_in[3];
    const float* eps       = (const float*)d_in[4];
    float* out = (float*)d_out;

    int n = in_sizes[3];                         // 4,194,304 — divisible by TILE_PIX
    int tiles = (n + TILE_PIX - 1) / TILE_PIX;   // 65536

    melnet_gmm_bulk64_kernel<<<tiles, THREADS>>>(mu, log_std, pi_logits,
                                                 u_cat, eps, out, n);
}